// round 5
// baseline (speedup 1.0000x reference)
#include <cuda_runtime.h>
#include <cstring>

#define NN 10000
#define FF 4
#define TT 137
#define EE 160000
#define DD 32
#define FT 548        // F*T floats per node row in x (row = [f][t], t contiguous)
#define SPITCH 138    // skewed shared pitch per feature (138*4 = 552 floats total)
#define CAP 64        // max in-degree capacity (Poisson(16): P(>=64) ~ 1e-19)

// ---------------- device scratch ----------------
__device__ int    g_deg[NN];
__device__ int    g_srcB[NN * CAP];
__device__ float  g_Mz[FF * DD];        // 0.5 * conv_w[0] @ lin_w[0,:D]
__device__ float  g_Mh[FF * DD];        //       conv_w[2] @ lin_w[2,:D]
__device__ float  g_bz[DD];
__device__ float  g_bh[DD];
__device__ float  g_probs[TT];

typedef unsigned long long u64;

__device__ __forceinline__ float tanh_approx(float x) {
    float y;
    asm("tanh.approx.f32 %0, %1;" : "=f"(y) : "f"(x));
    return y;
}
// Blackwell packed f32x2 ops (FFMA2 path — only reachable via PTX)
__device__ __forceinline__ u64 fma2(u64 a, u64 b, u64 c) {
    u64 d; asm("fma.rn.f32x2 %0, %1, %2, %3;" : "=l"(d) : "l"(a), "l"(b), "l"(c)); return d;
}
__device__ __forceinline__ u64 mul2(u64 a, u64 b) {
    u64 d; asm("mul.rn.f32x2 %0, %1, %2;" : "=l"(d) : "l"(a), "l"(b)); return d;
}
__device__ __forceinline__ u64 pack2(float lo, float hi) {
    u64 d; asm("mov.b64 %0, {%1, %2};" : "=l"(d) : "f"(lo), "f"(hi)); return d;
}
__device__ __forceinline__ void unpack2(u64 p, float& lo, float& hi) {
    asm("mov.b64 {%0, %1}, %2;" : "=f"(lo), "=f"(hi) : "l"(p));
}

// ---------------- kernel 1: zero degrees + prep (weights/softmax/out) ----------------
__global__ void k_init(const float* __restrict__ cw, const float* __restrict__ cb,
                       const float* __restrict__ lw, const float* __restrict__ lb,
                       const float* __restrict__ att, const float* __restrict__ b2,
                       float* out) {
    int b = blockIdx.x;
    if (b < 40) {
        int i = b * 256 + threadIdx.x;
        if (i < NN) g_deg[i] = 0;
        return;
    }
    // ---- prep block ----
    int tid = threadIdx.x;
    int lane = tid & 31, wid = tid >> 5;
    if (wid == 0 || wid == 1) {
        // wid 0 -> gate z (g=0, scaled 0.5 for tanh identity), wid 1 -> gate h (g=2)
        int g = (wid == 0) ? 0 : 2;
        float scale = (wid == 0) ? 0.5f : 1.0f;
        const float* cwg = cw + g * (FF * DD);
        const float* cbg = cb + g * DD;
        const float* lwg = lw + g * (2 * DD * DD);   // rows [0,D)
        const float* lbg = lb + g * DD;
        float* M = (wid == 0) ? g_Mz : g_Mh;
        float* B = (wid == 0) ? g_bz : g_bh;
        int d = lane;
#pragma unroll
        for (int f = 0; f < FF; f++) {
            float s = 0.0f;
#pragma unroll
            for (int k = 0; k < DD; k++)
                s += cwg[f * DD + k] * lwg[k * DD + d];
            M[f * DD + d] = scale * s;
        }
        float s = lbg[d];
#pragma unroll
        for (int k = 0; k < DD; k++)
            s += cbg[k] * lwg[k * DD + d];
        B[d] = scale * s;
    } else if (wid == 2) {
        // softmax over attention[137]
        float m = -1e30f;
        for (int t = lane; t < TT; t += 32) m = fmaxf(m, att[t]);
#pragma unroll
        for (int o = 16; o; o >>= 1) m = fmaxf(m, __shfl_xor_sync(0xffffffffu, m, o));
        float s = 0.0f;
        for (int t = lane; t < TT; t += 32) s += expf(att[t] - m);
#pragma unroll
        for (int o = 16; o; o >>= 1) s += __shfl_xor_sync(0xffffffffu, s, o);
        float inv = 1.0f / s;
        for (int t = lane; t < TT; t += 32) g_probs[t] = expf(att[t] - m) * inv;
    } else if (tid == 96) {
        out[0] = b2[0];   // everything else accumulates on top via atomics
    }
}

// ---------------- kernel 2: count+fill buckets ----------------
__global__ void k_build(const int* __restrict__ row, const int* __restrict__ col) {
    int e = blockIdx.x * blockDim.x + threadIdx.x;
    if (e < EE) {
        int c = col[e];
        int p = atomicAdd(&g_deg[c], 1);
        if (p < CAP) g_srcB[c * CAP + p] = row[e];
    }
}

// ---------------- kernel 3: fused gather + GRU-gate + attention + head ----------------
// One warp per node. Grid = NN/8 blocks of 256 threads (8 warps).
__global__ __launch_bounds__(256) void k_main(const float* __restrict__ x,
                                              const float* __restrict__ w1,
                                              const float* __restrict__ b1,
                                              const float* __restrict__ w2,
                                              float* __restrict__ out) {
    __shared__ __align__(8) float sa[8][FF * SPITCH];   // skewed: elem e -> e + e/137
    __shared__ __align__(8) float sprobs[TT + 1];

    int tid = threadIdx.x;
    int warp = tid >> 5, lane = tid & 31;
    int n = blockIdx.x * 8 + warp;   // grid sized exactly: always < NN

    for (int i = tid; i < TT; i += 256) sprobs[i] = g_probs[i];
    if (tid == 0) sprobs[TT] = 0.0f;
    __syncthreads();

    // -------- gather: agg[n] = dinv[n] * sum_src dinv[src]*x[src] + dinv[n]^2 * x[n]
    int deg = g_deg[n];
    float dn = rsqrtf((float)(deg + 1));
    const int* bucket = g_srcB + n * CAP;
    bool tail = (lane < 9);          // 137 float4s per row: indices 128..136 -> 9 lanes

    // accumulators: 5 float4 chunks as packed f32x2 pairs
    u64 acc[5][2];
#pragma unroll
    for (int c = 0; c < 5; c++) { acc[c][0] = 0ull; acc[c][1] = 0ull; }

    for (int j = 0; j < deg; j++) {
        int s = bucket[j];
        float w = rsqrtf((float)(g_deg[s] + 1));
        u64 wp = pack2(w, w);
        const longlong2* xs = (const longlong2*)(x + (size_t)s * FT);  // 2 u64 per float4
#pragma unroll
        for (int c = 0; c < 4; c++) {
            longlong2 v = __ldg(&xs[lane + 32 * c]);
            acc[c][0] = fma2(wp, (u64)v.x, acc[c][0]);
            acc[c][1] = fma2(wp, (u64)v.y, acc[c][1]);
        }
        if (tail) {
            longlong2 v = __ldg(&xs[lane + 128]);
            acc[4][0] = fma2(wp, (u64)v.x, acc[4][0]);
            acc[4][1] = fma2(wp, (u64)v.y, acc[4][1]);
        }
    }
    {   // fold self term: acc = dn*acc + dn2*x[n], then store skewed to shared
        u64 dnp  = pack2(dn, dn);
        u64 dn2p = pack2(dn * dn, dn * dn);
        const longlong2* xn = (const longlong2*)(x + (size_t)n * FT);
        float* sp = sa[warp];
#pragma unroll
        for (int c = 0; c < 5; c++) {
            if (c == 4 && !tail) break;
            longlong2 v = __ldg(&xn[lane + 32 * c]);
            acc[c][0] = fma2(acc[c][0], dnp, mul2(dn2p, (u64)v.x));
            acc[c][1] = fma2(acc[c][1], dnp, mul2(dn2p, (u64)v.y));
            float f0, f1, f2, f3;
            unpack2(acc[c][0], f0, f1);
            unpack2(acc[c][1], f2, f3);
            int e = 4 * (lane + 32 * c);
            sp[e     + (e    ) / TT] = f0;
            sp[e + 1 + (e + 1) / TT] = f1;
            sp[e + 2 + (e + 2) / TT] = f2;
            sp[e + 3 + (e + 3) / TT] = f3;
        }
    }
    __syncwarp();

    // -------- gate phase: lane = output dim d, pairs of t via f32x2
    // (1 - sigmoid(zx)) * tanh(hx) = (0.5 - 0.5*tanh(zx/2)) * tanh(hx); Mz/bz carry the 0.5
    int d = lane;
    u64 mz0 = pack2(g_Mz[d], g_Mz[d]),           mz1 = pack2(g_Mz[32 + d], g_Mz[32 + d]);
    u64 mz2 = pack2(g_Mz[64 + d], g_Mz[64 + d]), mz3 = pack2(g_Mz[96 + d], g_Mz[96 + d]);
    u64 mh0 = pack2(g_Mh[d], g_Mh[d]),           mh1 = pack2(g_Mh[32 + d], g_Mh[32 + d]);
    u64 mh2 = pack2(g_Mh[64 + d], g_Mh[64 + d]), mh3 = pack2(g_Mh[96 + d], g_Mh[96 + d]);
    u64 bzp = pack2(g_bz[d], g_bz[d]),           bhp = pack2(g_bh[d], g_bh[d]);
    const float* a = sa[warp];

    float hs = 0.0f;
#pragma unroll 2
    for (int t = 0; t < TT - 1; t += 2) {
        u64 v0 = *(const u64*)(a + t);
        u64 v1 = *(const u64*)(a + SPITCH + t);
        u64 v2 = *(const u64*)(a + 2 * SPITCH + t);
        u64 v3 = *(const u64*)(a + 3 * SPITCH + t);
        u64 q  = fma2(v3, mz3, fma2(v2, mz2, fma2(v1, mz1, fma2(v0, mz0, bzp))));
        u64 hx = fma2(v3, mh3, fma2(v2, mh2, fma2(v1, mh1, fma2(v0, mh0, bhp))));
        float q0, q1, h0, h1;
        unpack2(q, q0, q1);
        unpack2(hx, h0, h1);
        float2 pr = *(const float2*)(sprobs + t);
        float val0 = fmaf(-0.5f, tanh_approx(q0), 0.5f) * tanh_approx(h0);
        float val1 = fmaf(-0.5f, tanh_approx(q1), 0.5f) * tanh_approx(h1);
        hs = fmaf(val0, pr.x, hs);
        hs = fmaf(val1, pr.y, hs);
    }
    {   // tail t = 136
        const int t = TT - 1;
        float v0 = a[t], v1 = a[SPITCH + t], v2 = a[2 * SPITCH + t], v3 = a[3 * SPITCH + t];
        float mzs0, mzd; unpack2(mz0, mzs0, mzd);
        float q  = fmaf(v3, g_Mz[96 + d], fmaf(v2, g_Mz[64 + d], fmaf(v1, g_Mz[32 + d], fmaf(v0, g_Mz[d], g_bz[d]))));
        float hx = fmaf(v3, g_Mh[96 + d], fmaf(v2, g_Mh[64 + d], fmaf(v1, g_Mh[32 + d], fmaf(v0, g_Mh[d], g_bh[d]))));
        float val = fmaf(-0.5f, tanh_approx(q), 0.5f) * tanh_approx(hx);
        hs = fmaf(val, sprobs[t], hs);
    }

    // relu -> dot w1 -> +b1 -> * w2[n] -> accumulate
    float r = fmaxf(hs, 0.0f) * w1[d];
#pragma unroll
    for (int o = 16; o; o >>= 1) r += __shfl_xor_sync(0xffffffffu, r, o);
    if (lane == 0)
        atomicAdd(out, (r + b1[0]) * w2[n]);
}

// ---------------- launch ----------------
extern "C" void kernel_launch(void* const* d_in, const int* in_sizes, int n_in,
                              void* d_out, int out_size) {
    const float* x    = (const float*)d_in[0];
    const int*   ei   = (const int*)  d_in[1];
    const float* cw   = (const float*)d_in[2];
    const float* cb   = (const float*)d_in[3];
    const float* lw   = (const float*)d_in[4];
    const float* lb   = (const float*)d_in[5];
    const float* att  = (const float*)d_in[6];
    const float* w1   = (const float*)d_in[7];
    const float* b1   = (const float*)d_in[8];
    const float* w2   = (const float*)d_in[9];
    const float* b2   = (const float*)d_in[10];
    float* out = (float*)d_out;

    const int* row = ei;
    const int* col = ei + EE;

    k_init<<<41, 256>>>(cw, cb, lw, lb, att, b2, out);
    k_build<<<(EE + 255) / 256, 256>>>(row, col);
    k_main<<<NN / 8, 256>>>(x, w1, b1, w2, out);
}